// round 3
// baseline (speedup 1.0000x reference)
#include <cuda_runtime.h>
#include <stdint.h>

#define NUM_CLASSES 100000
#define EMBED_DIM   512
#define BATCH       16384

// -------------------------------------------------------------------------
// Kernel B: per-batch-row gather + loss + scatter-add.
//   block b handles batch row b. 128 threads, each owns 4 consecutive floats.
//   d = feature - center (pre-update center)
//   loss += d*d ;  out_center_row += 0.05 * d  (atomic, duplicates rare)
// -------------------------------------------------------------------------
__global__ __launch_bounds__(128)
void center_update_kernel(const float* __restrict__ features,
                          const int* __restrict__ labels,     // int32 (JAX x64 disabled)
                          const float* __restrict__ center_var,
                          float* __restrict__ out_centers,
                          float* __restrict__ loss_out) {
    const int b = blockIdx.x;
    const int t = threadIdx.x;

    const long long lbl = (long long)labels[b];

    const float4* frow = reinterpret_cast<const float4*>(features + (long long)b * EMBED_DIM);
    const float4* crow = reinterpret_cast<const float4*>(center_var + lbl * EMBED_DIM);
    float* orow = out_centers + lbl * EMBED_DIM;   // 4-byte aligned only; scalar atomics OK

    float4 f = frow[t];
    float4 c = crow[t];

    float dx = f.x - c.x;
    float dy = f.y - c.y;
    float dz = f.z - c.z;
    float dw = f.w - c.w;

    // scatter-add: update = -(1-ALPHA)*(c - f) = 0.05*(f - c)
    const float scale = 1.0f - 0.95f;
    atomicAdd(orow + 4 * t + 0, scale * dx);
    atomicAdd(orow + 4 * t + 1, scale * dy);
    atomicAdd(orow + 4 * t + 2, scale * dz);
    atomicAdd(orow + 4 * t + 3, scale * dw);

    // loss partial: sum of squared diffs
    float s = dx * dx + dy * dy + dz * dz + dw * dw;

    // warp reduce
    #pragma unroll
    for (int off = 16; off > 0; off >>= 1)
        s += __shfl_down_sync(0xFFFFFFFFu, s, off);

    __shared__ float warp_sums[4];
    if ((t & 31) == 0) warp_sums[t >> 5] = s;
    __syncthreads();

    if (t == 0) {
        float blk = warp_sums[0] + warp_sums[1] + warp_sums[2] + warp_sums[3];
        const float inv_n = 1.0f / ((float)BATCH * (float)EMBED_DIM);
        atomicAdd(loss_out, blk * inv_n);
    }
}

// -------------------------------------------------------------------------
// Launch
// -------------------------------------------------------------------------
extern "C" void kernel_launch(void* const* d_in, const int* in_sizes, int n_in,
                              void* d_out, int out_size) {
    const float* features   = (const float*)d_in[0];
    const int*   labels     = (const int*)d_in[1];
    const float* center_var = (const float*)d_in[2];

    float* out = (float*)d_out;
    float* loss_out    = out;       // out[0] = loss
    float* out_centers = out + 1;   // out[1:] = new_centers (4-byte aligned)

    // Zero the loss accumulator (4 bytes).
    cudaMemsetAsync(loss_out, 0, sizeof(float), 0);

    // Copy center_var -> out_centers. Driver memcpy handles the misaligned
    // (out+1) destination; D2D async memcpy is graph-capturable.
    cudaMemcpyAsync(out_centers, center_var,
                    (size_t)NUM_CLASSES * EMBED_DIM * sizeof(float),
                    cudaMemcpyDeviceToDevice, 0);

    // Kernel B: one block per batch row (same stream -> runs after the copy).
    center_update_kernel<<<BATCH, 128>>>(
        features, labels, center_var, out_centers, loss_out);
}